// round 4
// baseline (speedup 1.0000x reference)
#include <cuda_runtime.h>
#include <cstdint>

#define N_NODES 50000
#define N_EDGES 800000
#define N_RELS  200
#define D       128
#define D4      (D/4)

// Scratch (allocation-free rule: __device__ globals)
__device__ float g_hn[N_NODES * D];    // h * norm
__device__ float g_agg[N_NODES * D];   // norm * segment_sum(hn[src]-r[rel], dst)
__device__ int   g_cnt[N_NODES];       // per-dst degree (INVARIANT: zero at entry; scan resets)
__device__ int   g_off[N_NODES + 1];   // CSR offsets
__device__ int   g_cur[N_NODES];       // running fill cursors
__device__ int   g_ekey[N_EDGES];      // packed (src<<8)|rel, bucketed by dst

// ---------------------------------------------------------------------------
// f32x2 helpers (packed FFMA — PTX-only, ptxas never auto-fuses)
// ---------------------------------------------------------------------------
typedef unsigned long long u64;

__device__ __forceinline__ u64 pack_dup(float x) {
    unsigned r = __float_as_uint(x);
    u64 d;
    asm("mov.b64 %0, {%1, %1};" : "=l"(d) : "r"(r));
    return d;
}
__device__ __forceinline__ u64 ffma2(u64 a, u64 b, u64 c) {
    u64 d;
    asm("fma.rn.f32x2 %0, %1, %2, %3;" : "=l"(d) : "l"(a), "l"(b), "l"(c));
    return d;
}
__device__ __forceinline__ float2 unpack2(u64 p) {
    unsigned lo, hi;
    asm("mov.b64 {%0, %1}, %2;" : "=r"(lo), "=r"(hi) : "l"(p));
    return make_float2(__uint_as_float(lo), __uint_as_float(hi));
}

// ---------------------------------------------------------------------------
// Kernel 1 (fused): hn = h * norm  AND  histogram of dst into g_cnt.
// g_cnt is zero on entry (static init at load; k_scan resets it each run).
// ---------------------------------------------------------------------------
__global__ void k_prep_hist(const float* __restrict__ h,
                            const float* __restrict__ norm,
                            const int*   __restrict__ dst) {
    int i = blockIdx.x * blockDim.x + threadIdx.x;
    if (i < N_EDGES) atomicAdd(&g_cnt[__ldg(dst + i)], 1);
    if (i >= N_NODES * D4) return;
    int row = i / D4;
    float n = __ldg(norm + row);
    float4 v = reinterpret_cast<const float4*>(h)[i];
    v.x *= n; v.y *= n; v.z *= n; v.w *= n;
    reinterpret_cast<float4*>(g_hn)[i] = v;
}

// ---------------------------------------------------------------------------
// Kernel 2: single-block exclusive scan of g_cnt -> g_off/g_cur.
// 1024 threads, ~49 nodes each. Also resets g_cnt to 0 (self-resetting
// invariant) and writes the sentinel g_off[N_NODES].
// ---------------------------------------------------------------------------
#define SCAN_T 1024
#define SCAN_PER ((N_NODES + SCAN_T - 1) / SCAN_T)   // 49

__global__ __launch_bounds__(SCAN_T, 1)
void k_scan() {
    __shared__ int ssum[SCAN_T];
    const int tid = threadIdx.x;
    const int base = tid * SCAN_PER;

    int s = 0;
    #pragma unroll 7
    for (int i = 0; i < SCAN_PER; i++) {
        int idx = base + i;
        if (idx < N_NODES) s += g_cnt[idx];
    }
    ssum[tid] = s;
    __syncthreads();

    // Hillis-Steele inclusive scan over 1024 partial sums
    #pragma unroll
    for (int ofs = 1; ofs < SCAN_T; ofs <<= 1) {
        int t = (tid >= ofs) ? ssum[tid - ofs] : 0;
        __syncthreads();
        ssum[tid] += t;
        __syncthreads();
    }

    int run = ssum[tid] - s;   // exclusive prefix for this thread's chunk
    #pragma unroll 7
    for (int i = 0; i < SCAN_PER; i++) {
        int idx = base + i;
        if (idx < N_NODES) {
            int c = g_cnt[idx];
            g_off[idx] = run;
            g_cur[idx] = run;
            g_cnt[idx] = 0;        // restore invariant for next replay
            run += c;
        }
    }
    if (tid == 0) g_off[N_NODES] = N_EDGES;
}

// ---------------------------------------------------------------------------
// Kernel 3: CSR fill — bucket packed (src<<8)|rel keys by dst.
// ---------------------------------------------------------------------------
__global__ void k_fill(const int* __restrict__ src,
                       const int* __restrict__ dst,
                       const int* __restrict__ rel) {
    int e = blockIdx.x * blockDim.x + threadIdx.x;
    if (e >= N_EDGES) return;
    int d = __ldg(dst + e);
    int pos = atomicAdd(&g_cur[d], 1);
    g_ekey[pos] = (__ldg(src + e) << 8) | __ldg(rel + e);
}

// ---------------------------------------------------------------------------
// Kernel 4: gather — one warp per dst node, register accumulation, no atomics.
//   g_agg[n] = norm[n] * sum_{e in CSR[n]} (hn[src_e] - r[rel_e])
// Unrolled x4 for MLP (8 outstanding float4 gathers per warp).
// ---------------------------------------------------------------------------
__global__ void k_gather(const float* __restrict__ r,
                         const float* __restrict__ norm) {
    int warp = (blockIdx.x * blockDim.x + threadIdx.x) >> 5;
    int lane = threadIdx.x & 31;
    if (warp >= N_NODES) return;

    int e0 = __ldg(g_off + warp);
    int e1 = __ldg(g_off + warp + 1);

    const float4* hn4 = reinterpret_cast<const float4*>(g_hn);
    const float4* r4  = reinterpret_cast<const float4*>(r);

    float4 acc0 = make_float4(0.f, 0.f, 0.f, 0.f);
    float4 acc1 = make_float4(0.f, 0.f, 0.f, 0.f);

    int e = e0;
    for (; e + 4 <= e1; e += 4) {
        int k0 = __ldg(g_ekey + e);
        int k1 = __ldg(g_ekey + e + 1);
        int k2 = __ldg(g_ekey + e + 2);
        int k3 = __ldg(g_ekey + e + 3);
        float4 h0 = __ldg(hn4 + (k0 >> 8) * D4 + lane);
        float4 h1 = __ldg(hn4 + (k1 >> 8) * D4 + lane);
        float4 h2 = __ldg(hn4 + (k2 >> 8) * D4 + lane);
        float4 h3 = __ldg(hn4 + (k3 >> 8) * D4 + lane);
        float4 v0 = __ldg(r4 + (k0 & 255) * D4 + lane);
        float4 v1 = __ldg(r4 + (k1 & 255) * D4 + lane);
        float4 v2 = __ldg(r4 + (k2 & 255) * D4 + lane);
        float4 v3 = __ldg(r4 + (k3 & 255) * D4 + lane);
        acc0.x += (h0.x - v0.x) + (h1.x - v1.x);
        acc0.y += (h0.y - v0.y) + (h1.y - v1.y);
        acc0.z += (h0.z - v0.z) + (h1.z - v1.z);
        acc0.w += (h0.w - v0.w) + (h1.w - v1.w);
        acc1.x += (h2.x - v2.x) + (h3.x - v3.x);
        acc1.y += (h2.y - v2.y) + (h3.y - v3.y);
        acc1.z += (h2.z - v2.z) + (h3.z - v3.z);
        acc1.w += (h2.w - v2.w) + (h3.w - v3.w);
    }
    for (; e < e1; e++) {
        int k0 = __ldg(g_ekey + e);
        float4 h0 = __ldg(hn4 + (k0 >> 8) * D4 + lane);
        float4 v0 = __ldg(r4 + (k0 & 255) * D4 + lane);
        acc0.x += h0.x - v0.x; acc0.y += h0.y - v0.y;
        acc0.z += h0.z - v0.z; acc0.w += h0.w - v0.w;
    }

    float nm = __ldg(norm + warp);
    float4 o;
    o.x = (acc0.x + acc1.x) * nm;
    o.y = (acc0.y + acc1.y) * nm;
    o.z = (acc0.z + acc1.z) * nm;
    o.w = (acc0.w + acc1.w) * nm;
    reinterpret_cast<float4*>(g_agg)[warp * D4 + lane] = o;
}

// ---------------------------------------------------------------------------
// Kernel 5: GEMM  out = relu( [hn | agg] @ [W ; W_msg] + b )
// Stacked weight (256x128) in smem; A tile 64x256 transposed in smem.
// Microkernel uses packed f32x2 FFMA: 16 FFMA2 per k per thread.
// ---------------------------------------------------------------------------
#define MT     64
#define SA_LD  66   // even: keeps float2 A-loads 8B-aligned
#define SMEM_GEMM ((256 * 128 + 256 * SA_LD) * (int)sizeof(float))  // 198,656 B

__global__ __launch_bounds__(256, 1)
void k_gemm(const float* __restrict__ W_msg,
            const float* __restrict__ W,
            const float* __restrict__ b,
            float* __restrict__ out) {
    extern __shared__ float smem[];
    float* sW = smem;              // [256][128]
    float* sA = smem + 256 * 128;  // [256][SA_LD]

    const int tid = threadIdx.x;
    const int tileBase = blockIdx.x * MT;

    // stacked weights: k 0..127 = W, 128..255 = W_msg
    {
        const float4* W4  = reinterpret_cast<const float4*>(W);
        const float4* Wm4 = reinterpret_cast<const float4*>(W_msg);
        float4* sW4 = reinterpret_cast<float4*>(sW);
        #pragma unroll
        for (int i = tid; i < 256 * 32; i += 256)
            sW4[i] = (i < 128 * 32) ? __ldg(W4 + i) : __ldg(Wm4 + (i - 128 * 32));
    }

    // A tile transposed: k 0..127 = hn, k 128..255 = agg (norm pre-applied)
    for (int i = tid; i < MT * 32; i += 256) {
        int rr = i / 32, k4 = i % 32;
        int row = tileBase + rr;
        float4 v = make_float4(0.f, 0.f, 0.f, 0.f);
        if (row < N_NODES) v = reinterpret_cast<const float4*>(g_hn)[row * D4 + k4];
        sA[(k4 * 4 + 0) * SA_LD + rr] = v.x;
        sA[(k4 * 4 + 1) * SA_LD + rr] = v.y;
        sA[(k4 * 4 + 2) * SA_LD + rr] = v.z;
        sA[(k4 * 4 + 3) * SA_LD + rr] = v.w;
    }
    for (int i = tid; i < MT * 32; i += 256) {
        int rr = i / 32, k4 = i % 32;
        int row = tileBase + rr;
        float4 v = make_float4(0.f, 0.f, 0.f, 0.f);
        if (row < N_NODES) v = reinterpret_cast<const float4*>(g_agg)[row * D4 + k4];
        sA[(128 + k4 * 4 + 0) * SA_LD + rr] = v.x;
        sA[(128 + k4 * 4 + 1) * SA_LD + rr] = v.y;
        sA[(128 + k4 * 4 + 2) * SA_LD + rr] = v.z;
        sA[(128 + k4 * 4 + 3) * SA_LD + rr] = v.w;
    }
    __syncthreads();

    const int tcol = tid & 15;    // 16 col groups of 4 (x2 halves)
    const int trow = tid >> 4;    // 16 row groups of 4
    const int r0 = trow * 4;

    u64 acc[4][4];                // [row][colpair]
    #pragma unroll
    for (int rr = 0; rr < 4; rr++)
        #pragma unroll
        for (int cp = 0; cp < 4; cp++) acc[rr][cp] = 0ull;

    #pragma unroll 4
    for (int k = 0; k < 256; k++) {
        ulonglong2 w0 = *reinterpret_cast<const ulonglong2*>(&sW[k * 128 + tcol * 4]);
        ulonglong2 w1 = *reinterpret_cast<const ulonglong2*>(&sW[k * 128 + 64 + tcol * 4]);
        float2 a01 = *reinterpret_cast<const float2*>(&sA[k * SA_LD + r0]);
        float2 a23 = *reinterpret_cast<const float2*>(&sA[k * SA_LD + r0 + 2]);
        u64 ad[4];
        ad[0] = pack_dup(a01.x);
        ad[1] = pack_dup(a01.y);
        ad[2] = pack_dup(a23.x);
        ad[3] = pack_dup(a23.y);
        #pragma unroll
        for (int rr = 0; rr < 4; rr++) {
            acc[rr][0] = ffma2(ad[rr], w0.x, acc[rr][0]);
            acc[rr][1] = ffma2(ad[rr], w0.y, acc[rr][1]);
            acc[rr][2] = ffma2(ad[rr], w1.x, acc[rr][2]);
            acc[rr][3] = ffma2(ad[rr], w1.y, acc[rr][3]);
        }
    }

    // epilogue: + b, relu, store
    const int c0 = tcol * 4;
    float4 b0 = __ldg(reinterpret_cast<const float4*>(b) + c0 / 4);
    float4 b1 = __ldg(reinterpret_cast<const float4*>(b) + (c0 + 64) / 4);
    #pragma unroll
    for (int rr = 0; rr < 4; rr++) {
        int row = tileBase + r0 + rr;
        if (row >= N_NODES) break;
        float2 p0 = unpack2(acc[rr][0]);
        float2 p1 = unpack2(acc[rr][1]);
        float2 p2 = unpack2(acc[rr][2]);
        float2 p3 = unpack2(acc[rr][3]);
        float4 o0, o1;
        o0.x = fmaxf(p0.x + b0.x, 0.f);
        o0.y = fmaxf(p0.y + b0.y, 0.f);
        o0.z = fmaxf(p1.x + b0.z, 0.f);
        o0.w = fmaxf(p1.y + b0.w, 0.f);
        o1.x = fmaxf(p2.x + b1.x, 0.f);
        o1.y = fmaxf(p2.y + b1.y, 0.f);
        o1.z = fmaxf(p3.x + b1.z, 0.f);
        o1.w = fmaxf(p3.y + b1.w, 0.f);
        reinterpret_cast<float4*>(out)[row * D4 + c0 / 4] = o0;
        reinterpret_cast<float4*>(out)[row * D4 + (c0 + 64) / 4] = o1;
    }
}

// ---------------------------------------------------------------------------
extern "C" void kernel_launch(void* const* d_in, const int* in_sizes, int n_in,
                              void* d_out, int out_size) {
    const float* h     = (const float*)d_in[0];
    const float* r     = (const float*)d_in[1];
    const float* norm  = (const float*)d_in[2];
    const int*   src   = (const int*)d_in[3];
    const int*   dst   = (const int*)d_in[4];
    const int*   rel   = (const int*)d_in[5];
    const float* W_msg = (const float*)d_in[6];
    const float* W     = (const float*)d_in[7];
    const float* b     = (const float*)d_in[8];
    float* out = (float*)d_out;

    // fused prep + dst histogram (g_cnt is zero on entry, see k_scan)
    k_prep_hist<<<(N_NODES * D4 + 255) / 256, 256>>>(h, norm, dst);

    // single-block scan: offsets + cursors, resets g_cnt
    k_scan<<<1, SCAN_T>>>();

    // CSR fill
    k_fill<<<(N_EDGES + 255) / 256, 256>>>(src, dst, rel);

    // gather (one warp per node)
    k_gather<<<(N_NODES * 32 + 255) / 256, 256>>>(r, norm);

    // fused GEMM + epilogue
    cudaFuncSetAttribute(k_gemm, cudaFuncAttributeMaxDynamicSharedMemorySize, SMEM_GEMM);
    k_gemm<<<(N_NODES + MT - 1) / MT, 256, SMEM_GEMM>>>(W_msg, W, b, out);
}

// round 5
// speedup vs baseline: 1.4838x; 1.4838x over previous
#include <cuda_runtime.h>
#include <cstdint>

#define N_NODES 50000
#define N_EDGES 800000
#define N_RELS  200
#define D       128
#define D4      (D/4)

#define SCAN_T   1024
#define N_CHUNKS ((N_NODES + SCAN_T - 1) / SCAN_T)   // 49

// Scratch (allocation-free rule: __device__ globals)
__device__ float g_hn[N_NODES * D];    // h * norm
__device__ float g_agg[N_NODES * D];   // norm * segment_sum(hn[src]-r[rel], dst)
__device__ int   g_cnt[N_NODES];       // per-dst degree (INVARIANT: zero at entry; scan1 resets)
__device__ int   g_off[N_NODES + 1];   // CSR offsets
__device__ int   g_cur[N_NODES];       // running fill cursors
__device__ int   g_ekey[N_EDGES];      // packed (src<<8)|rel, bucketed by dst
__device__ int   g_bsum[64];           // per-chunk sums

// ---------------------------------------------------------------------------
// f32x2 helpers (packed FFMA — PTX-only, ptxas never auto-fuses)
// ---------------------------------------------------------------------------
typedef unsigned long long u64;

__device__ __forceinline__ u64 pack_dup(float x) {
    unsigned r = __float_as_uint(x);
    u64 d;
    asm("mov.b64 %0, {%1, %1};" : "=l"(d) : "r"(r));
    return d;
}
__device__ __forceinline__ u64 ffma2(u64 a, u64 b, u64 c) {
    u64 d;
    asm("fma.rn.f32x2 %0, %1, %2, %3;" : "=l"(d) : "l"(a), "l"(b), "l"(c));
    return d;
}
__device__ __forceinline__ float2 unpack2(u64 p) {
    unsigned lo, hi;
    asm("mov.b64 {%0, %1}, %2;" : "=r"(lo), "=r"(hi) : "l"(p));
    return make_float2(__uint_as_float(lo), __uint_as_float(hi));
}

// ---------------------------------------------------------------------------
// Kernel 1 (fused): hn = h * norm  AND  histogram of dst into g_cnt.
// g_cnt is zero on entry (static zero-init at load; k_scan1 resets each run).
// ---------------------------------------------------------------------------
__global__ void k_prep_hist(const float* __restrict__ h,
                            const float* __restrict__ norm,
                            const int*   __restrict__ dst) {
    int i = blockIdx.x * blockDim.x + threadIdx.x;
    if (i < N_EDGES) atomicAdd(&g_cnt[__ldg(dst + i)], 1);
    if (i >= N_NODES * D4) return;
    int row = i / D4;
    float n = __ldg(norm + row);
    float4 v = reinterpret_cast<const float4*>(h)[i];
    v.x *= n; v.y *= n; v.z *= n; v.w *= n;
    reinterpret_cast<float4*>(g_hn)[i] = v;
}

// ---------------------------------------------------------------------------
// Kernel 2a: per-chunk scan (COALESCED: tid-indexed). Resets g_cnt.
// ---------------------------------------------------------------------------
__global__ __launch_bounds__(SCAN_T, 1)
void k_scan1() {
    __shared__ int s[SCAN_T];
    int tid = threadIdx.x;
    int idx = blockIdx.x * SCAN_T + tid;
    int v = (idx < N_NODES) ? g_cnt[idx] : 0;
    if (idx < N_NODES) g_cnt[idx] = 0;     // restore invariant (coalesced)
    s[tid] = v;
    __syncthreads();
    #pragma unroll
    for (int ofs = 1; ofs < SCAN_T; ofs <<= 1) {
        int t = (tid >= ofs) ? s[tid - ofs] : 0;
        __syncthreads();
        s[tid] += t;
        __syncthreads();
    }
    if (idx < N_NODES) g_off[idx] = s[tid] - v;   // exclusive (chunk-local)
    if (tid == SCAN_T - 1) g_bsum[blockIdx.x] = s[tid];
}

// ---------------------------------------------------------------------------
// Kernel 2b: add chunk prefix (each block computes it from g_bsum in smem),
// write final offsets + cursors. All accesses coalesced.
// ---------------------------------------------------------------------------
__global__ __launch_bounds__(SCAN_T, 1)
void k_scan2() {
    __shared__ int sb[64];
    int tid = threadIdx.x;
    if (tid < N_CHUNKS) sb[tid] = g_bsum[tid];
    __syncthreads();
    int prefix = 0;
    for (int i = 0; i < blockIdx.x; i++) prefix += sb[i];
    int idx = blockIdx.x * SCAN_T + tid;
    if (idx < N_NODES) {
        int o = g_off[idx] + prefix;
        g_off[idx] = o;
        g_cur[idx] = o;
    }
    if (idx == 0) g_off[N_NODES] = N_EDGES;
}

// ---------------------------------------------------------------------------
// Kernel 3: CSR fill — bucket packed (src<<8)|rel keys by dst.
// ---------------------------------------------------------------------------
__global__ void k_fill(const int* __restrict__ src,
                       const int* __restrict__ dst,
                       const int* __restrict__ rel) {
    int e = blockIdx.x * blockDim.x + threadIdx.x;
    if (e >= N_EDGES) return;
    int d = __ldg(dst + e);
    int pos = atomicAdd(&g_cur[d], 1);
    g_ekey[pos] = (__ldg(src + e) << 8) | __ldg(rel + e);
}

// ---------------------------------------------------------------------------
// Kernel 4: gather — one warp per dst node, register accumulation, no atomics.
//   g_agg[n] = norm[n] * sum_{e in CSR[n]} (hn[src_e] - r[rel_e])
// Unrolled x4 for MLP (8 outstanding float4 gathers per warp).
// ---------------------------------------------------------------------------
__global__ void k_gather(const float* __restrict__ r,
                         const float* __restrict__ norm) {
    int warp = (blockIdx.x * blockDim.x + threadIdx.x) >> 5;
    int lane = threadIdx.x & 31;
    if (warp >= N_NODES) return;

    int e0 = __ldg(g_off + warp);
    int e1 = __ldg(g_off + warp + 1);

    const float4* hn4 = reinterpret_cast<const float4*>(g_hn);
    const float4* r4  = reinterpret_cast<const float4*>(r);

    float4 acc0 = make_float4(0.f, 0.f, 0.f, 0.f);
    float4 acc1 = make_float4(0.f, 0.f, 0.f, 0.f);

    int e = e0;
    for (; e + 4 <= e1; e += 4) {
        int k0 = __ldg(g_ekey + e);
        int k1 = __ldg(g_ekey + e + 1);
        int k2 = __ldg(g_ekey + e + 2);
        int k3 = __ldg(g_ekey + e + 3);
        float4 h0 = __ldg(hn4 + (k0 >> 8) * D4 + lane);
        float4 h1 = __ldg(hn4 + (k1 >> 8) * D4 + lane);
        float4 h2 = __ldg(hn4 + (k2 >> 8) * D4 + lane);
        float4 h3 = __ldg(hn4 + (k3 >> 8) * D4 + lane);
        float4 v0 = __ldg(r4 + (k0 & 255) * D4 + lane);
        float4 v1 = __ldg(r4 + (k1 & 255) * D4 + lane);
        float4 v2 = __ldg(r4 + (k2 & 255) * D4 + lane);
        float4 v3 = __ldg(r4 + (k3 & 255) * D4 + lane);
        acc0.x += (h0.x - v0.x) + (h1.x - v1.x);
        acc0.y += (h0.y - v0.y) + (h1.y - v1.y);
        acc0.z += (h0.z - v0.z) + (h1.z - v1.z);
        acc0.w += (h0.w - v0.w) + (h1.w - v1.w);
        acc1.x += (h2.x - v2.x) + (h3.x - v3.x);
        acc1.y += (h2.y - v2.y) + (h3.y - v3.y);
        acc1.z += (h2.z - v2.z) + (h3.z - v3.z);
        acc1.w += (h2.w - v2.w) + (h3.w - v3.w);
    }
    for (; e < e1; e++) {
        int k0 = __ldg(g_ekey + e);
        float4 h0 = __ldg(hn4 + (k0 >> 8) * D4 + lane);
        float4 v0 = __ldg(r4 + (k0 & 255) * D4 + lane);
        acc0.x += h0.x - v0.x; acc0.y += h0.y - v0.y;
        acc0.z += h0.z - v0.z; acc0.w += h0.w - v0.w;
    }

    float nm = __ldg(norm + warp);
    float4 o;
    o.x = (acc0.x + acc1.x) * nm;
    o.y = (acc0.y + acc1.y) * nm;
    o.z = (acc0.z + acc1.z) * nm;
    o.w = (acc0.w + acc1.w) * nm;
    reinterpret_cast<float4*>(g_agg)[warp * D4 + lane] = o;
}

// ---------------------------------------------------------------------------
// Kernel 5: GEMM  out = relu( [hn | agg] @ [W ; W_msg] + b )
// Stacked weight (256x128) in smem; A tile 64x256 transposed in smem.
// Microkernel uses packed f32x2 FFMA: 16 FFMA2 per k per thread.
// ---------------------------------------------------------------------------
#define MT     64
#define SA_LD  66   // even: keeps float2 A-loads 8B-aligned
#define SMEM_GEMM ((256 * 128 + 256 * SA_LD) * (int)sizeof(float))  // 198,656 B

__global__ __launch_bounds__(256, 1)
void k_gemm(const float* __restrict__ W_msg,
            const float* __restrict__ W,
            const float* __restrict__ b,
            float* __restrict__ out) {
    extern __shared__ float smem[];
    float* sW = smem;              // [256][128]
    float* sA = smem + 256 * 128;  // [256][SA_LD]

    const int tid = threadIdx.x;
    const int tileBase = blockIdx.x * MT;

    // stacked weights: k 0..127 = W, 128..255 = W_msg
    {
        const float4* W4  = reinterpret_cast<const float4*>(W);
        const float4* Wm4 = reinterpret_cast<const float4*>(W_msg);
        float4* sW4 = reinterpret_cast<float4*>(sW);
        #pragma unroll
        for (int i = tid; i < 256 * 32; i += 256)
            sW4[i] = (i < 128 * 32) ? __ldg(W4 + i) : __ldg(Wm4 + (i - 128 * 32));
    }

    // A tile transposed: k 0..127 = hn, k 128..255 = agg (norm pre-applied)
    for (int i = tid; i < MT * 32; i += 256) {
        int rr = i / 32, k4 = i % 32;
        int row = tileBase + rr;
        float4 v = make_float4(0.f, 0.f, 0.f, 0.f);
        if (row < N_NODES) v = reinterpret_cast<const float4*>(g_hn)[row * D4 + k4];
        sA[(k4 * 4 + 0) * SA_LD + rr] = v.x;
        sA[(k4 * 4 + 1) * SA_LD + rr] = v.y;
        sA[(k4 * 4 + 2) * SA_LD + rr] = v.z;
        sA[(k4 * 4 + 3) * SA_LD + rr] = v.w;
    }
    for (int i = tid; i < MT * 32; i += 256) {
        int rr = i / 32, k4 = i % 32;
        int row = tileBase + rr;
        float4 v = make_float4(0.f, 0.f, 0.f, 0.f);
        if (row < N_NODES) v = reinterpret_cast<const float4*>(g_agg)[row * D4 + k4];
        sA[(128 + k4 * 4 + 0) * SA_LD + rr] = v.x;
        sA[(128 + k4 * 4 + 1) * SA_LD + rr] = v.y;
        sA[(128 + k4 * 4 + 2) * SA_LD + rr] = v.z;
        sA[(128 + k4 * 4 + 3) * SA_LD + rr] = v.w;
    }
    __syncthreads();

    const int tcol = tid & 15;    // 16 col groups of 4 (x2 halves)
    const int trow = tid >> 4;    // 16 row groups of 4
    const int r0 = trow * 4;

    u64 acc[4][4];                // [row][colpair]
    #pragma unroll
    for (int rr = 0; rr < 4; rr++)
        #pragma unroll
        for (int cp = 0; cp < 4; cp++) acc[rr][cp] = 0ull;

    #pragma unroll 4
    for (int k = 0; k < 256; k++) {
        ulonglong2 w0 = *reinterpret_cast<const ulonglong2*>(&sW[k * 128 + tcol * 4]);
        ulonglong2 w1 = *reinterpret_cast<const ulonglong2*>(&sW[k * 128 + 64 + tcol * 4]);
        float2 a01 = *reinterpret_cast<const float2*>(&sA[k * SA_LD + r0]);
        float2 a23 = *reinterpret_cast<const float2*>(&sA[k * SA_LD + r0 + 2]);
        u64 ad[4];
        ad[0] = pack_dup(a01.x);
        ad[1] = pack_dup(a01.y);
        ad[2] = pack_dup(a23.x);
        ad[3] = pack_dup(a23.y);
        #pragma unroll
        for (int rr = 0; rr < 4; rr++) {
            acc[rr][0] = ffma2(ad[rr], w0.x, acc[rr][0]);
            acc[rr][1] = ffma2(ad[rr], w0.y, acc[rr][1]);
            acc[rr][2] = ffma2(ad[rr], w1.x, acc[rr][2]);
            acc[rr][3] = ffma2(ad[rr], w1.y, acc[rr][3]);
        }
    }

    // epilogue: + b, relu, store
    const int c0 = tcol * 4;
    float4 b0 = __ldg(reinterpret_cast<const float4*>(b) + c0 / 4);
    float4 b1 = __ldg(reinterpret_cast<const float4*>(b) + (c0 + 64) / 4);
    #pragma unroll
    for (int rr = 0; rr < 4; rr++) {
        int row = tileBase + r0 + rr;
        if (row >= N_NODES) break;
        float2 p0 = unpack2(acc[rr][0]);
        float2 p1 = unpack2(acc[rr][1]);
        float2 p2 = unpack2(acc[rr][2]);
        float2 p3 = unpack2(acc[rr][3]);
        float4 o0, o1;
        o0.x = fmaxf(p0.x + b0.x, 0.f);
        o0.y = fmaxf(p0.y + b0.y, 0.f);
        o0.z = fmaxf(p1.x + b0.z, 0.f);
        o0.w = fmaxf(p1.y + b0.w, 0.f);
        o1.x = fmaxf(p2.x + b1.x, 0.f);
        o1.y = fmaxf(p2.y + b1.y, 0.f);
        o1.z = fmaxf(p3.x + b1.z, 0.f);
        o1.w = fmaxf(p3.y + b1.w, 0.f);
        reinterpret_cast<float4*>(out)[row * D4 + c0 / 4] = o0;
        reinterpret_cast<float4*>(out)[row * D4 + (c0 + 64) / 4] = o1;
    }
}

// ---------------------------------------------------------------------------
extern "C" void kernel_launch(void* const* d_in, const int* in_sizes, int n_in,
                              void* d_out, int out_size) {
    const float* h     = (const float*)d_in[0];
    const float* r     = (const float*)d_in[1];
    const float* norm  = (const float*)d_in[2];
    const int*   src   = (const int*)d_in[3];
    const int*   dst   = (const int*)d_in[4];
    const int*   rel   = (const int*)d_in[5];
    const float* W_msg = (const float*)d_in[6];
    const float* W     = (const float*)d_in[7];
    const float* b     = (const float*)d_in[8];
    float* out = (float*)d_out;

    // fused prep + dst histogram (g_cnt is zero on entry; k_scan1 resets it)
    k_prep_hist<<<(N_NODES * D4 + 255) / 256, 256>>>(h, norm, dst);

    // coalesced two-phase scan: offsets + cursors
    k_scan1<<<N_CHUNKS, SCAN_T>>>();
    k_scan2<<<N_CHUNKS, SCAN_T>>>();

    // CSR fill
    k_fill<<<(N_EDGES + 255) / 256, 256>>>(src, dst, rel);

    // gather (one warp per node)
    k_gather<<<(N_NODES * 32 + 255) / 256, 256>>>(r, norm);

    // fused GEMM + epilogue
    cudaFuncSetAttribute(k_gemm, cudaFuncAttributeMaxDynamicSharedMemorySize, SMEM_GEMM);
    k_gemm<<<(N_NODES + MT - 1) / MT, 256, SMEM_GEMM>>>(W_msg, W, b, out);
}

// round 7
// speedup vs baseline: 2.5064x; 1.6892x over previous
#include <cuda_runtime.h>
#include <cstdint>

#define N_NODES 50000
#define N_EDGES 800000
#define N_RELS  200
#define D       128
#define D4      (D/4)

#define SCAN_T   1024
#define N_CHUNKS ((N_NODES + SCAN_T - 1) / SCAN_T)   // 49

// Scratch (allocation-free rule: __device__ globals)
__device__ float g_hn[N_NODES * D];    // h * norm
__device__ float g_agg[N_NODES * D];   // norm * segment_sum(hn[src]-r[rel], dst)
__device__ int   g_cnt[N_NODES];       // per-dst degree (INVARIANT: zero at entry; scan1 resets)
__device__ int   g_off[N_NODES + 1];   // CSR offsets
__device__ int   g_cur[N_NODES];       // running fill cursors
__device__ int   g_ekey[N_EDGES];      // packed (src<<8)|rel, bucketed by dst
__device__ int   g_bsum[64];           // per-chunk sums

// ---------------------------------------------------------------------------
// tf32 helpers (baseline PTX, no 'a' features)
// ---------------------------------------------------------------------------
__device__ __forceinline__ uint32_t f2tf32(float f) {
    uint32_t t;
    asm("cvt.rna.tf32.f32 %0, %1;" : "=r"(t) : "f"(f));
    return t;
}
__device__ __forceinline__ void mma_tf32(float* c, const uint32_t* a, const uint32_t* b) {
    asm volatile(
        "mma.sync.aligned.m16n8k8.row.col.f32.tf32.tf32.f32 "
        "{%0,%1,%2,%3}, {%4,%5,%6,%7}, {%8,%9}, {%0,%1,%2,%3};"
        : "+f"(c[0]), "+f"(c[1]), "+f"(c[2]), "+f"(c[3])
        : "r"(a[0]), "r"(a[1]), "r"(a[2]), "r"(a[3]), "r"(b[0]), "r"(b[1]));
}

// ---------------------------------------------------------------------------
// Kernel 1 (fused): hn = h * norm ; dst histogram.
// g_cnt is zero on entry (static zero-init at load; k_scan1 resets each run).
// ---------------------------------------------------------------------------
__global__ void k_prep_hist(const float* __restrict__ h,
                            const float* __restrict__ norm,
                            const int*   __restrict__ dst) {
    int i = blockIdx.x * blockDim.x + threadIdx.x;
    if (i < N_EDGES) atomicAdd(&g_cnt[__ldg(dst + i)], 1);
    if (i >= N_NODES * D4) return;
    int row = i / D4;
    float nrm = __ldg(norm + row);
    float4 v = reinterpret_cast<const float4*>(h)[i];
    v.x *= nrm; v.y *= nrm; v.z *= nrm; v.w *= nrm;
    reinterpret_cast<float4*>(g_hn)[i] = v;
}

// ---------------------------------------------------------------------------
// Kernel 2a: per-chunk scan (coalesced). Resets g_cnt.
// ---------------------------------------------------------------------------
__global__ __launch_bounds__(SCAN_T, 1)
void k_scan1() {
    __shared__ int s[SCAN_T];
    int tid = threadIdx.x;
    int idx = blockIdx.x * SCAN_T + tid;
    int v = (idx < N_NODES) ? g_cnt[idx] : 0;
    if (idx < N_NODES) g_cnt[idx] = 0;
    s[tid] = v;
    __syncthreads();
    #pragma unroll
    for (int ofs = 1; ofs < SCAN_T; ofs <<= 1) {
        int t = (tid >= ofs) ? s[tid - ofs] : 0;
        __syncthreads();
        s[tid] += t;
        __syncthreads();
    }
    if (idx < N_NODES) g_off[idx] = s[tid] - v;
    if (tid == SCAN_T - 1) g_bsum[blockIdx.x] = s[tid];
}

// ---------------------------------------------------------------------------
// Kernel 2b: add chunk prefix, write offsets + cursors.
// ---------------------------------------------------------------------------
__global__ __launch_bounds__(SCAN_T, 1)
void k_scan2() {
    __shared__ int sb[64];
    int tid = threadIdx.x;
    if (tid < N_CHUNKS) sb[tid] = g_bsum[tid];
    __syncthreads();
    int prefix = 0;
    for (int i = 0; i < blockIdx.x; i++) prefix += sb[i];
    int idx = blockIdx.x * SCAN_T + tid;
    if (idx < N_NODES) {
        int o = g_off[idx] + prefix;
        g_off[idx] = o;
        g_cur[idx] = o;
    }
    if (idx == 0) g_off[N_NODES] = N_EDGES;
}

// ---------------------------------------------------------------------------
// Kernel 3: CSR fill — 2 edges per thread (2 independent ATOMG in flight).
// ---------------------------------------------------------------------------
__global__ void k_fill(const int* __restrict__ src,
                       const int* __restrict__ dst,
                       const int* __restrict__ rel) {
    int t = blockIdx.x * blockDim.x + threadIdx.x;
    int e0 = t * 2, e1 = t * 2 + 1;
    if (e0 >= N_EDGES) return;
    int d0 = __ldg(dst + e0);
    int k0 = (__ldg(src + e0) << 8) | __ldg(rel + e0);
    if (e1 < N_EDGES) {
        int d1 = __ldg(dst + e1);
        int k1 = (__ldg(src + e1) << 8) | __ldg(rel + e1);
        int p0 = atomicAdd(&g_cur[d0], 1);
        int p1 = atomicAdd(&g_cur[d1], 1);
        g_ekey[p0] = k0;
        g_ekey[p1] = k1;
    } else {
        g_ekey[atomicAdd(&g_cur[d0], 1)] = k0;
    }
}

// ---------------------------------------------------------------------------
// Kernel 4: gather — one warp per dst node, register accumulation.
// hn gathers via __ldcg (L2-only, keep r-table L1-resident).
// ---------------------------------------------------------------------------
__global__ void k_gather(const float* __restrict__ r,
                         const float* __restrict__ norm) {
    int warp = (blockIdx.x * blockDim.x + threadIdx.x) >> 5;
    int lane = threadIdx.x & 31;
    if (warp >= N_NODES) return;

    int e0 = __ldg(g_off + warp);
    int e1 = __ldg(g_off + warp + 1);

    const float4* hn4 = reinterpret_cast<const float4*>(g_hn);
    const float4* r4  = reinterpret_cast<const float4*>(r);

    float4 acc0 = make_float4(0.f, 0.f, 0.f, 0.f);
    float4 acc1 = make_float4(0.f, 0.f, 0.f, 0.f);

    int e = e0;
    for (; e + 4 <= e1; e += 4) {
        int k0 = __ldg(g_ekey + e);
        int k1 = __ldg(g_ekey + e + 1);
        int k2 = __ldg(g_ekey + e + 2);
        int k3 = __ldg(g_ekey + e + 3);
        float4 h0 = __ldcg(hn4 + (k0 >> 8) * D4 + lane);
        float4 h1 = __ldcg(hn4 + (k1 >> 8) * D4 + lane);
        float4 h2 = __ldcg(hn4 + (k2 >> 8) * D4 + lane);
        float4 h3 = __ldcg(hn4 + (k3 >> 8) * D4 + lane);
        float4 v0 = __ldg(r4 + (k0 & 255) * D4 + lane);
        float4 v1 = __ldg(r4 + (k1 & 255) * D4 + lane);
        float4 v2 = __ldg(r4 + (k2 & 255) * D4 + lane);
        float4 v3 = __ldg(r4 + (k3 & 255) * D4 + lane);
        acc0.x += (h0.x - v0.x) + (h1.x - v1.x);
        acc0.y += (h0.y - v0.y) + (h1.y - v1.y);
        acc0.z += (h0.z - v0.z) + (h1.z - v1.z);
        acc0.w += (h0.w - v0.w) + (h1.w - v1.w);
        acc1.x += (h2.x - v2.x) + (h3.x - v3.x);
        acc1.y += (h2.y - v2.y) + (h3.y - v3.y);
        acc1.z += (h2.z - v2.z) + (h3.z - v3.z);
        acc1.w += (h2.w - v2.w) + (h3.w - v3.w);
    }
    for (; e < e1; e++) {
        int k0 = __ldg(g_ekey + e);
        float4 h0 = __ldcg(hn4 + (k0 >> 8) * D4 + lane);
        float4 v0 = __ldg(r4 + (k0 & 255) * D4 + lane);
        acc0.x += h0.x - v0.x; acc0.y += h0.y - v0.y;
        acc0.z += h0.z - v0.z; acc0.w += h0.w - v0.w;
    }

    float nm = __ldg(norm + warp);
    float4 o;
    o.x = (acc0.x + acc1.x) * nm;
    o.y = (acc0.y + acc1.y) * nm;
    o.z = (acc0.z + acc1.z) * nm;
    o.w = (acc0.w + acc1.w) * nm;
    reinterpret_cast<float4*>(g_agg)[warp * D4 + lane] = o;
}

// ---------------------------------------------------------------------------
// Kernel 5: tf32 mma.sync GEMM  out = relu( [hn | agg] @ [W ; W_msg] + b )
// Block tile 128 rows x 128 cols, 8 warps; warp = 32 rows x 64 cols
//   = 2 m16 tiles x 8 n8 tiles, k-step 8, K = 256.
// smem: sB [256][136] tf32 (full stacked weight, conflict-free bank map 8*tg+g)
//       sA 2 x [128][36] tf32 (k-chunks of 32, double-buffered, bank map 4g+tg)
// ---------------------------------------------------------------------------
#define LDB 136
#define LDA 36
#define SB_WORDS (256 * LDB)          // 34816
#define SA_WORDS (128 * LDA)          // 4608 per buffer
#define SMEM_TC  ((SB_WORDS + 2 * SA_WORDS) * 4)   // 176,128 bytes

__global__ __launch_bounds__(256, 1)
void k_gemm_tc(const float* __restrict__ W,
               const float* __restrict__ W_msg,
               const float* __restrict__ bias,
               float* __restrict__ out) {
    extern __shared__ uint32_t smw[];
    uint32_t* sB = smw;                 // [256][LDB]
    uint32_t* sA = smw + SB_WORDS;      // 2 x [128][LDA]

    const int tid = threadIdx.x;
    const int wid = tid >> 5;
    const int lane = tid & 31;
    const int g  = lane >> 2;           // 0..7
    const int tg = lane & 3;            // 0..3
    const int tileBase = blockIdx.x * 128;
    const int wrb = (wid & 3) * 32;     // warp row base in tile
    const int wcb = (wid >> 2) * 64;    // warp col base

    // --- load B: rows k 0..127 = W[k][n], 128..255 = W_msg[k-128][n] (tf32) ---
    {
        #pragma unroll
        for (int i = tid; i < 256 * 32; i += 256) {
            int k = i >> 5, f4 = i & 31;
            const float4* srcp = (k < 128)
                ? reinterpret_cast<const float4*>(W) + k * 32 + f4
                : reinterpret_cast<const float4*>(W_msg) + (k - 128) * 32 + f4;
            float4 v = __ldg(srcp);
            uint4 t;
            t.x = f2tf32(v.x); t.y = f2tf32(v.y);
            t.z = f2tf32(v.z); t.w = f2tf32(v.w);
            *reinterpret_cast<uint4*>(sB + k * LDB + f4 * 4) = t;
        }
    }

    // --- A chunk loader: chunk c<4 from hn, c>=4 from agg (32 k each, tf32) ---
    auto loadA = [&](int c, uint32_t* buf) {
        const float4* src = reinterpret_cast<const float4*>((c < 4) ? g_hn : g_agg);
        int kc = (c & 3) * 8;                    // float4 offset within 32-f4 row
        #pragma unroll
        for (int i = tid; i < 128 * 8; i += 256) {
            int row = i >> 3, f4 = i & 7;
            int gr = tileBase + row;
            float4 v = make_float4(0.f, 0.f, 0.f, 0.f);
            if (gr < N_NODES) v = __ldcg(src + gr * 32 + kc + f4);
            uint4 t;
            t.x = f2tf32(v.x); t.y = f2tf32(v.y);
            t.z = f2tf32(v.z); t.w = f2tf32(v.w);
            *reinterpret_cast<uint4*>(buf + row * LDA + f4 * 4) = t;
        }
    };

    float acc[2][8][4];
    #pragma unroll
    for (int mt = 0; mt < 2; mt++)
        #pragma unroll
        for (int nt = 0; nt < 8; nt++)
            #pragma unroll
            for (int cc = 0; cc < 4; cc++) acc[mt][nt][cc] = 0.f;

    loadA(0, sA);
    __syncthreads();

    #pragma unroll
    for (int c = 0; c < 8; c++) {
        if (c + 1 < 8) loadA(c + 1, sA + ((c + 1) & 1) * SA_WORDS);
        const uint32_t* A = sA + (c & 1) * SA_WORDS;
        const uint32_t* Bc = sB + c * 32 * LDB;

        #pragma unroll
        for (int ks = 0; ks < 4; ks++) {
            int k0 = ks * 8;
            uint32_t afr[2][4];
            #pragma unroll
            for (int mt = 0; mt < 2; mt++) {
                int rb = wrb + mt * 16 + g;
                afr[mt][0] = A[rb * LDA + k0 + tg];
                afr[mt][1] = A[(rb + 8) * LDA + k0 + tg];
                afr[mt][2] = A[rb * LDA + k0 + tg + 4];
                afr[mt][3] = A[(rb + 8) * LDA + k0 + tg + 4];
            }
            #pragma unroll
            for (int nt = 0; nt < 8; nt++) {
                uint32_t bfr[2];
                int ncol = wcb + nt * 8 + g;
                bfr[0] = Bc[(k0 + tg) * LDB + ncol];
                bfr[1] = Bc[(k0 + tg + 4) * LDB + ncol];
                mma_tf32(acc[0][nt], afr[0], bfr);
                mma_tf32(acc[1][nt], afr[1], bfr);
            }
        }
        __syncthreads();
    }

    // --- epilogue: + b, relu, store (float2 per c-pair) ---
    #pragma unroll
    for (int mt = 0; mt < 2; mt++) {
        int r0 = tileBase + wrb + mt * 16 + g;
        int r1 = r0 + 8;
        #pragma unroll
        for (int nt = 0; nt < 8; nt++) {
            int col = wcb + nt * 8 + tg * 2;
            float2 bb = *reinterpret_cast<const float2*>(bias + col);
            if (r0 < N_NODES) {
                float2 o;
                o.x = fmaxf(acc[mt][nt][0] + bb.x, 0.f);
                o.y = fmaxf(acc[mt][nt][1] + bb.y, 0.f);
                *reinterpret_cast<float2*>(out + r0 * D + col) = o;
            }
            if (r1 < N_NODES) {
                float2 o;
                o.x = fmaxf(acc[mt][nt][2] + bb.x, 0.f);
                o.y = fmaxf(acc[mt][nt][3] + bb.y, 0.f);
                *reinterpret_cast<float2*>(out + r1 * D + col) = o;
            }
        }
    }
}

// ---------------------------------------------------------------------------
extern "C" void kernel_launch(void* const* d_in, const int* in_sizes, int n_in,
                              void* d_out, int out_size) {
    const float* h     = (const float*)d_in[0];
    const float* r     = (const float*)d_in[1];
    const float* norm  = (const float*)d_in[2];
    const int*   src   = (const int*)d_in[3];
    const int*   dst   = (const int*)d_in[4];
    const int*   rel   = (const int*)d_in[5];
    const float* W_msg = (const float*)d_in[6];
    const float* W     = (const float*)d_in[7];
    const float* b     = (const float*)d_in[8];
    float* out = (float*)d_out;

    // fused prep: hn + dst histogram (g_cnt zero on entry; k_scan1 resets it)
    k_prep_hist<<<(N_NODES * D4 + 255) / 256, 256>>>(h, norm, dst);

    // coalesced two-phase scan: offsets + cursors
    k_scan1<<<N_CHUNKS, SCAN_T>>>();
    k_scan2<<<N_CHUNKS, SCAN_T>>>();

    // CSR fill (2 edges/thread)
    k_fill<<<(N_EDGES / 2 + 255) / 256, 256>>>(src, dst, rel);

    // gather (one warp per node)
    k_gather<<<(N_NODES * 32 + 255) / 256, 256>>>(r, norm);

    // tf32 mma.sync GEMM + epilogue
    cudaFuncSetAttribute(k_gemm_tc, cudaFuncAttributeMaxDynamicSharedMemorySize, SMEM_TC);
    k_gemm_tc<<<(N_NODES + 127) / 128, 256, SMEM_TC>>>(W, W_msg, b, out);
}